// round 3
// baseline (speedup 1.0000x reference)
#include <cuda_runtime.h>
#include <cuda_bf16.h>

#define BATCH  4
#define SEQ    2048
#define DMODEL 1024
#define NSTATE 16
#define SEG    32                  // segment length
#define NSEGS  (SEQ / SEG)         // 64 segments
#define NCH    (BATCH * DMODEL)    // 4096 channels

// ---------------- device scratch (static: no allocation) ----------------
__device__ float  g_c[SEG];                   // c_k = b^T A^k b
__device__ float  g_vrev[SEG][NSTATE];        // vrev[s] = A^{SEG-1-s} b
__device__ float  g_Q[SEG][NSTATE];           // Q[r]  = b^T A^{r+1}
__device__ float  g_A32[NSTATE * NSTATE];     // A^SEG
__device__ float4 g_V4[NSEGS * NCH * 4];      // injected state  [g][ch][16]   (16.8 MB)
__device__ float4 g_H4[NSEGS * NCH * 4];      // entry states    [g][ch][16]   (16.8 MB)

// ---------------- K0: precompute filter taps and transition powers ----------------
__global__ void __launch_bounds__(256) k0_precompute(const float* __restrict__ A,
                                                     const float* __restrict__ bvec) {
    __shared__ float sA[NSTATE * NSTATE];
    __shared__ float M[2][NSTATE * NSTATE];
    __shared__ float sb[NSTATE];
    const int tid = threadIdx.x;            // 256 threads
    sA[tid] = A[tid];
    if (tid < NSTATE) sb[tid] = bvec[tid];
    M[0][tid] = ((tid >> 4) == (tid & 15)) ? 1.f : 0.f;   // M = I
    __syncthreads();

    int cur = 0;
    const int row = tid >> 4, col = tid & 15;
    for (int j = 0; j < SEG; ++j) {         // at loop top: M[cur] = A^j
        if (tid < NSTATE) {                 // vrev[SEG-1-j] = A^j b
            float a = 0.f;
            #pragma unroll
            for (int n = 0; n < NSTATE; ++n) a = fmaf(M[cur][tid * NSTATE + n], sb[n], a);
            g_vrev[SEG - 1 - j][tid] = a;
        } else if (tid < 32 && j >= 1) {    // Q[j-1] = b^T A^j
            const int m = tid - NSTATE;
            float a = 0.f;
            #pragma unroll
            for (int k = 0; k < NSTATE; ++k) a = fmaf(sb[k], M[cur][k * NSTATE + m], a);
            g_Q[j - 1][m] = a;
        }
        float a = 0.f;                      // M[1-cur] = M[cur] * A
        #pragma unroll
        for (int k = 0; k < NSTATE; ++k)
            a = fmaf(M[cur][row * NSTATE + k], sA[k * NSTATE + col], a);
        M[1 - cur][tid] = a;
        __syncthreads();
        cur ^= 1;
    }
    // M[cur] = A^SEG
    g_A32[tid] = M[cur][tid];
    if (tid < NSTATE) {                     // Q[SEG-1] = b^T A^SEG
        float a = 0.f;
        #pragma unroll
        for (int k = 0; k < NSTATE; ++k) a = fmaf(sb[k], M[cur][k * NSTATE + tid], a);
        g_Q[SEG - 1][tid] = a;
    }
    if (tid < SEG) {                        // c_k = b . A^k b
        float a = 0.f;
        #pragma unroll
        for (int m = 0; m < NSTATE; ++m) a = fmaf(sb[m], g_vrev[SEG - 1 - tid][m], a);
        g_c[tid] = a;
    }
}

// ---------------- K1: per-(channel,segment) local conv + injected state ----------------
__global__ void __launch_bounds__(256) k1_local(const float* __restrict__ x,
                                                float* __restrict__ out) {
    __shared__ float sc[SEG];
    __shared__ float sv[SEG][NSTATE];
    const int tid = threadIdx.x;
    if (tid < SEG) sc[tid] = g_c[tid];
    for (int i = tid; i < SEG * NSTATE; i += 256)
        (&sv[0][0])[i] = (&g_vrev[0][0])[i];
    __syncthreads();

    const int bid = blockIdx.x;             // 1024 blocks = 4 d-tiles * 4 batch * 64 segs
    const int d   = (bid & 3) * 256 + tid;
    const int b   = (bid >> 2) & 3;
    const int g   = bid >> 4;

    const size_t base = ((size_t)b * SEQ + (size_t)g * SEG) * DMODEL + d;
    const float* xp = x + base;
    float xs[SEG];
    #pragma unroll
    for (int s = 0; s < SEG; ++s) xs[s] = xp[(size_t)s * DMODEL];

    // triangular local convolution, 16 outputs at a time
    float* op = out + base;
    #pragma unroll
    for (int rb = 0; rb < SEG; rb += 16) {
        float acc[16];
        #pragma unroll
        for (int i = 0; i < 16; ++i) acc[i] = 0.f;
        #pragma unroll
        for (int s = 0; s < SEG; ++s) {
            if (s >= rb + 16) break;
            const float xv = xs[s];
            #pragma unroll
            for (int i = 0; i < 16; ++i) {
                const int r = rb + i;
                if (s <= r) acc[i] = fmaf(sc[r - s], xv, acc[i]);
            }
        }
        #pragma unroll
        for (int i = 0; i < 16; ++i) op[(size_t)(rb + i) * DMODEL] = acc[i];
    }

    // injected state V = sum_s A^{SEG-1-s} b x_s
    float V[NSTATE];
    #pragma unroll
    for (int m = 0; m < NSTATE; ++m) V[m] = 0.f;
    #pragma unroll
    for (int s = 0; s < SEG; ++s) {
        const float xv = xs[s];
        #pragma unroll
        for (int m = 0; m < NSTATE; ++m) V[m] = fmaf(sv[s][m], xv, V[m]);
    }
    const int ch = b * DMODEL + d;
    float4* vp = g_V4 + ((size_t)g * NCH + ch) * 4;
    vp[0] = make_float4(V[0],  V[1],  V[2],  V[3]);
    vp[1] = make_float4(V[4],  V[5],  V[6],  V[7]);
    vp[2] = make_float4(V[8],  V[9],  V[10], V[11]);
    vp[3] = make_float4(V[12], V[13], V[14], V[15]);
}

// ---------------- K2: fused sequential prefix over segments ----------------
// 16 lanes per channel (lane = state dim m). H_{g+1} = A32 H_g + V_g; store entry states.
__global__ void __launch_bounds__(256) k2_prefix(void) {
    const int tid = threadIdx.x;
    const int m   = tid & 15;
    const int ch  = (blockIdx.x * 256 + tid) >> 4;     // 256 blocks -> 4096 channels

    // row m of A32 in registers
    float ar[NSTATE];
    #pragma unroll
    for (int n = 0; n < NSTATE; ++n) ar[n] = g_A32[m * NSTATE + n];

    const float* Vs = (const float*)g_V4;
    float*       Hs = (float*)g_H4;

    float h = 0.f;
    for (int g = 0; g < NSEGS; ++g) {
        const size_t off = ((size_t)g * NCH + ch) * NSTATE + m;   // coalesced
        Hs[off] = h;                                   // entry state of segment g
        const float v = Vs[off];
        // hnew = v + sum_n ar[n] * h_other(n)   (4 partial accumulators)
        float a0 = v, a1 = 0.f, a2 = 0.f, a3 = 0.f;
        #pragma unroll
        for (int n = 0; n < NSTATE; n += 4) {
            a0 = fmaf(ar[n + 0], __shfl_sync(0xffffffffu, h, n + 0, 16), a0);
            a1 = fmaf(ar[n + 1], __shfl_sync(0xffffffffu, h, n + 1, 16), a1);
            a2 = fmaf(ar[n + 2], __shfl_sync(0xffffffffu, h, n + 2, 16), a2);
            a3 = fmaf(ar[n + 3], __shfl_sync(0xffffffffu, h, n + 3, 16), a3);
        }
        h = (a0 + a1) + (a2 + a3);
    }
}

// ---------------- K3: add entering-state contribution  y += Q[r] . H_seg ----------------
__global__ void __launch_bounds__(256) k3_correct(float* __restrict__ out) {
    __shared__ float sQ[SEG][NSTATE];
    const int tid = threadIdx.x;
    for (int i = tid; i < SEG * NSTATE; i += 256)
        (&sQ[0][0])[i] = (&g_Q[0][0])[i];
    __syncthreads();

    const size_t idx = (size_t)blockIdx.x * 256 + tid;    // 8.4M outputs
    const int d = (int)(idx & (DMODEL - 1));
    const int t = (int)((idx >> 10) & (SEQ - 1));
    const int b = (int)(idx >> 21);
    const int ch = b * DMODEL + d;
    const int g = t / SEG, r = t & (SEG - 1);

    const float4* hp = g_H4 + ((size_t)g * NCH + ch) * 4;  // contiguous 2KB per warp
    float4 h0 = hp[0], h1 = hp[1], h2 = hp[2], h3 = hp[3];

    float acc = out[idx];
    const float* q = &sQ[r][0];
    acc = fmaf(q[0],  h0.x, acc); acc = fmaf(q[1],  h0.y, acc);
    acc = fmaf(q[2],  h0.z, acc); acc = fmaf(q[3],  h0.w, acc);
    acc = fmaf(q[4],  h1.x, acc); acc = fmaf(q[5],  h1.y, acc);
    acc = fmaf(q[6],  h1.z, acc); acc = fmaf(q[7],  h1.w, acc);
    acc = fmaf(q[8],  h2.x, acc); acc = fmaf(q[9],  h2.y, acc);
    acc = fmaf(q[10], h2.z, acc); acc = fmaf(q[11], h2.w, acc);
    acc = fmaf(q[12], h3.x, acc); acc = fmaf(q[13], h3.y, acc);
    acc = fmaf(q[14], h3.z, acc); acc = fmaf(q[15], h3.w, acc);
    out[idx] = acc;
}

// ---------------- launch ----------------
extern "C" void kernel_launch(void* const* d_in, const int* in_sizes, int n_in,
                              void* d_out, int out_size) {
    const float* x = nullptr; const float* A = nullptr; const float* bv = nullptr;
    for (int i = 0; i < n_in; ++i) {
        if      (in_sizes[i] == BATCH * SEQ * DMODEL) x  = (const float*)d_in[i];
        else if (in_sizes[i] == NSTATE * NSTATE)      A  = (const float*)d_in[i];
        else if (in_sizes[i] == NSTATE)               bv = (const float*)d_in[i];
    }
    float* out = (float*)d_out;

    k0_precompute<<<1, 256>>>(A, bv);
    k1_local<<<(DMODEL / 256) * BATCH * NSEGS, 256>>>(x, out);   // 1024 blocks
    k2_prefix<<<(NCH * NSTATE) / 256, 256>>>();                  // 256 blocks
    k3_correct<<<(BATCH * SEQ * DMODEL) / 256, 256>>>(out);      // 32768 blocks
}

// round 4
// speedup vs baseline: 2.7741x; 2.7741x over previous
#include <cuda_runtime.h>
#include <cuda_bf16.h>

#define BATCH  4
#define SEQ    2048
#define DMODEL 1024
#define NSTATE 16
#define SEG    32                  // segment length
#define NSEGS  (SEQ / SEG)         // 64 segments
#define NCH    (BATCH * DMODEL)    // 4096 channels

// ---------------- device scratch (static: no allocation) ----------------
__device__ float  g_c[SEG];                   // c_k = b^T A^k b
__device__ float  g_vrev[SEG][NSTATE];        // vrev[s] = A^{SEG-1-s} b
__device__ float  g_Q[SEG][NSTATE];           // Q[r]  = b^T A^{r+1}
__device__ float  g_A32[NSTATE * NSTATE];     // A^SEG
__device__ float4 g_V4[NSEGS * NCH * 4];      // injected state  [g][ch][16]   (16.8 MB)
__device__ float4 g_H4[NSEGS * NCH * 4];      // entry states    [g][ch][16]   (16.8 MB)

// ---------------- K0: precompute filter taps and transition powers ----------------
__global__ void __launch_bounds__(256) k0_precompute(const float* __restrict__ A,
                                                     const float* __restrict__ bvec) {
    __shared__ float sA[NSTATE * NSTATE];
    __shared__ float M[2][NSTATE * NSTATE];
    __shared__ float sb[NSTATE];
    const int tid = threadIdx.x;            // 256 threads
    sA[tid] = A[tid];
    if (tid < NSTATE) sb[tid] = bvec[tid];
    M[0][tid] = ((tid >> 4) == (tid & 15)) ? 1.f : 0.f;   // M = I
    __syncthreads();

    int cur = 0;
    const int row = tid >> 4, col = tid & 15;
    for (int j = 0; j < SEG; ++j) {         // at loop top: M[cur] = A^j
        if (tid < NSTATE) {                 // vrev[SEG-1-j] = A^j b
            float a = 0.f;
            #pragma unroll
            for (int n = 0; n < NSTATE; ++n) a = fmaf(M[cur][tid * NSTATE + n], sb[n], a);
            g_vrev[SEG - 1 - j][tid] = a;
        } else if (tid < 32 && j >= 1) {    // Q[j-1] = b^T A^j
            const int m = tid - NSTATE;
            float a = 0.f;
            #pragma unroll
            for (int k = 0; k < NSTATE; ++k) a = fmaf(sb[k], M[cur][k * NSTATE + m], a);
            g_Q[j - 1][m] = a;
        }
        float a = 0.f;                      // M[1-cur] = M[cur] * A
        #pragma unroll
        for (int k = 0; k < NSTATE; ++k)
            a = fmaf(M[cur][row * NSTATE + k], sA[k * NSTATE + col], a);
        M[1 - cur][tid] = a;
        __syncthreads();
        cur ^= 1;
    }
    // M[cur] = A^SEG
    g_A32[tid] = M[cur][tid];
    if (tid < NSTATE) {                     // Q[SEG-1] = b^T A^SEG
        float a = 0.f;
        #pragma unroll
        for (int k = 0; k < NSTATE; ++k) a = fmaf(sb[k], M[cur][k * NSTATE + tid], a);
        g_Q[SEG - 1][tid] = a;
    }
    if (tid < SEG) {                        // c_k = b . A^k b
        float a = 0.f;
        #pragma unroll
        for (int m = 0; m < NSTATE; ++m) a = fmaf(sb[m], g_vrev[SEG - 1 - tid][m], a);
        g_c[tid] = a;
    }
}

// ---------------- K1: per-(channel,segment) local conv + injected state ----------------
__global__ void __launch_bounds__(256) k1_local(const float* __restrict__ x,
                                                float* __restrict__ out) {
    __shared__ float sc[SEG];
    __shared__ float sv[SEG][NSTATE];
    const int tid = threadIdx.x;
    if (tid < SEG) sc[tid] = g_c[tid];
    for (int i = tid; i < SEG * NSTATE; i += 256)
        (&sv[0][0])[i] = (&g_vrev[0][0])[i];
    __syncthreads();

    const int bid = blockIdx.x;             // 1024 blocks = 4 d-tiles * 4 batch * 64 segs
    const int d   = (bid & 3) * 256 + tid;
    const int b   = (bid >> 2) & 3;
    const int g   = bid >> 4;

    const size_t base = ((size_t)b * SEQ + (size_t)g * SEG) * DMODEL + d;
    const float* xp = x + base;
    float xs[SEG];
    #pragma unroll
    for (int s = 0; s < SEG; ++s) xs[s] = xp[(size_t)s * DMODEL];

    // triangular local convolution, 16 outputs at a time
    float* op = out + base;
    #pragma unroll
    for (int rb = 0; rb < SEG; rb += 16) {
        float acc[16];
        #pragma unroll
        for (int i = 0; i < 16; ++i) acc[i] = 0.f;
        #pragma unroll
        for (int s = 0; s < SEG; ++s) {
            if (s >= rb + 16) break;
            const float xv = xs[s];
            #pragma unroll
            for (int i = 0; i < 16; ++i) {
                const int r = rb + i;
                if (s <= r) acc[i] = fmaf(sc[r - s], xv, acc[i]);
            }
        }
        #pragma unroll
        for (int i = 0; i < 16; ++i) op[(size_t)(rb + i) * DMODEL] = acc[i];
    }

    // injected state V = sum_s A^{SEG-1-s} b x_s
    float V[NSTATE];
    #pragma unroll
    for (int m = 0; m < NSTATE; ++m) V[m] = 0.f;
    #pragma unroll
    for (int s = 0; s < SEG; ++s) {
        const float xv = xs[s];
        #pragma unroll
        for (int m = 0; m < NSTATE; ++m) V[m] = fmaf(sv[s][m], xv, V[m]);
    }
    const int ch = b * DMODEL + d;
    float4* vp = g_V4 + ((size_t)g * NCH + ch) * 4;
    vp[0] = make_float4(V[0],  V[1],  V[2],  V[3]);
    vp[1] = make_float4(V[4],  V[5],  V[6],  V[7]);
    vp[2] = make_float4(V[8],  V[9],  V[10], V[11]);
    vp[3] = make_float4(V[12], V[13], V[14], V[15]);
}

// ---------------- K2: fused sequential prefix over segments ----------------
// 16 lanes per channel (lane = state dim m). H_{g+1} = A32 H_g + V_g; store entry states.
__global__ void __launch_bounds__(256) k2_prefix(void) {
    const int tid = threadIdx.x;
    const int m   = tid & 15;
    const int ch  = (blockIdx.x * 256 + tid) >> 4;     // 256 blocks -> 4096 channels

    // row m of A32 in registers
    float ar[NSTATE];
    #pragma unroll
    for (int n = 0; n < NSTATE; ++n) ar[n] = g_A32[m * NSTATE + n];

    const float* Vs = (const float*)g_V4;
    float*       Hs = (float*)g_H4;

    float h = 0.f;
    for (int g = 0; g < NSEGS; ++g) {
        const size_t off = ((size_t)g * NCH + ch) * NSTATE + m;   // coalesced
        Hs[off] = h;                                   // entry state of segment g
        const float v = Vs[off];
        float a0 = v, a1 = 0.f, a2 = 0.f, a3 = 0.f;
        #pragma unroll
        for (int n = 0; n < NSTATE; n += 4) {
            a0 = fmaf(ar[n + 0], __shfl_sync(0xffffffffu, h, n + 0, 16), a0);
            a1 = fmaf(ar[n + 1], __shfl_sync(0xffffffffu, h, n + 1, 16), a1);
            a2 = fmaf(ar[n + 2], __shfl_sync(0xffffffffu, h, n + 2, 16), a2);
            a3 = fmaf(ar[n + 3], __shfl_sync(0xffffffffu, h, n + 3, 16), a3);
        }
        h = (a0 + a1) + (a2 + a3);
    }
}

// ---------------- K3: add entering-state contribution  y += Q[r] . H_seg ----------------
// ONE thread per (channel, segment): H loaded once, reused for all 32 outputs.
__global__ void __launch_bounds__(256) k3_correct(float* __restrict__ out) {
    __shared__ float sQ[SEG][NSTATE];
    const int tid = threadIdx.x;
    for (int i = tid; i < SEG * NSTATE; i += 256)
        (&sQ[0][0])[i] = (&g_Q[0][0])[i];
    __syncthreads();

    const int job = blockIdx.x * 256 + tid;     // 262144 jobs = (ch, seg)
    const int d = job & (DMODEL - 1);
    const int b = (job >> 10) & 3;
    const int g = job >> 12;
    const int ch = b * DMODEL + d;

    // entry state H: 4x LDG.128, warp footprint = 2KB contiguous
    const float4* hp = g_H4 + ((size_t)g * NCH + ch) * 4;
    const float4 h0 = hp[0], h1 = hp[1], h2 = hp[2], h3 = hp[3];
    float H[NSTATE] = {h0.x, h0.y, h0.z, h0.w, h1.x, h1.y, h1.z, h1.w,
                       h2.x, h2.y, h2.z, h2.w, h3.x, h3.y, h3.z, h3.w};

    float* op = out + ((size_t)(b * SEQ + g * SEG)) * DMODEL + d;

    // 32 RMWs, 8 at a time (bounded live registers, batched independent loads)
    #pragma unroll
    for (int r0 = 0; r0 < SEG; r0 += 8) {
        float vals[8];
        #pragma unroll
        for (int i = 0; i < 8; ++i) vals[i] = op[(size_t)(r0 + i) * DMODEL];
        #pragma unroll
        for (int i = 0; i < 8; ++i) {
            float acc = vals[i];
            const float* q = &sQ[r0 + i][0];   // broadcast (same addr across warp)
            #pragma unroll
            for (int m = 0; m < NSTATE; ++m) acc = fmaf(q[m], H[m], acc);
            op[(size_t)(r0 + i) * DMODEL] = acc;
        }
    }
}

// ---------------- launch ----------------
extern "C" void kernel_launch(void* const* d_in, const int* in_sizes, int n_in,
                              void* d_out, int out_size) {
    const float* x = nullptr; const float* A = nullptr; const float* bv = nullptr;
    for (int i = 0; i < n_in; ++i) {
        if      (in_sizes[i] == BATCH * SEQ * DMODEL) x  = (const float*)d_in[i];
        else if (in_sizes[i] == NSTATE * NSTATE)      A  = (const float*)d_in[i];
        else if (in_sizes[i] == NSTATE)               bv = (const float*)d_in[i];
    }
    float* out = (float*)d_out;

    k0_precompute<<<1, 256>>>(A, bv);
    k1_local<<<(DMODEL / 256) * BATCH * NSEGS, 256>>>(x, out);   // 1024 blocks
    k2_prefix<<<(NCH * NSTATE) / 256, 256>>>();                  // 256 blocks
    k3_correct<<<(NCH * NSEGS) / 256, 256>>>(out);               // 1024 blocks
}

// round 5
// speedup vs baseline: 2.8399x; 1.0237x over previous
#include <cuda_runtime.h>
#include <cuda_bf16.h>

#define BATCH  4
#define SEQ    2048
#define DMODEL 1024
#define NSTATE 16
#define SEG    32                  // segment length
#define NSEGS  (SEQ / SEG)         // 64 segments
#define NCH    (BATCH * DMODEL)    // 4096 channels

// ---------------- device scratch (static: no allocation) ----------------
__device__ float  g_c[SEG];                   // c_k = b^T A^k b
__device__ float4 g_vrev4[SEG][4];            // vrev[s] = A^{SEG-1-s} b   (float4-packed)
__device__ float4 g_Q4[SEG][4];               // Q[r]  = b^T A^{r+1}      (float4-packed)
__device__ float  g_A32[NSTATE * NSTATE];     // A^SEG
__device__ float4 g_V4[NSEGS * NCH * 4];      // injected state  [g][ch][16]   (16.8 MB)
__device__ float4 g_H4[NSEGS * NCH * 4];      // entry states    [g][ch][16]   (16.8 MB)

// ---------------- K0: precompute filter taps and transition powers ----------------
__global__ void __launch_bounds__(256) k0_precompute(const float* __restrict__ A,
                                                     const float* __restrict__ bvec) {
    __shared__ float sA[NSTATE * NSTATE];
    __shared__ float M[2][NSTATE * NSTATE];
    __shared__ float sb[NSTATE];
    const int tid = threadIdx.x;            // 256 threads
    sA[tid] = A[tid];
    if (tid < NSTATE) sb[tid] = bvec[tid];
    M[0][tid] = ((tid >> 4) == (tid & 15)) ? 1.f : 0.f;   // M = I
    __syncthreads();

    float* vrev = (float*)g_vrev4;
    float* Q    = (float*)g_Q4;

    int cur = 0;
    const int row = tid >> 4, col = tid & 15;
    for (int j = 0; j < SEG; ++j) {         // at loop top: M[cur] = A^j
        if (tid < NSTATE) {                 // vrev[SEG-1-j] = A^j b
            float a = 0.f;
            #pragma unroll
            for (int n = 0; n < NSTATE; ++n) a = fmaf(M[cur][tid * NSTATE + n], sb[n], a);
            vrev[(SEG - 1 - j) * NSTATE + tid] = a;
        } else if (tid < 32 && j >= 1) {    // Q[j-1] = b^T A^j
            const int m = tid - NSTATE;
            float a = 0.f;
            #pragma unroll
            for (int k = 0; k < NSTATE; ++k) a = fmaf(sb[k], M[cur][k * NSTATE + m], a);
            Q[(j - 1) * NSTATE + m] = a;
        }
        float a = 0.f;                      // M[1-cur] = M[cur] * A
        #pragma unroll
        for (int k = 0; k < NSTATE; ++k)
            a = fmaf(M[cur][row * NSTATE + k], sA[k * NSTATE + col], a);
        M[1 - cur][tid] = a;
        __syncthreads();
        cur ^= 1;
    }
    // M[cur] = A^SEG
    g_A32[tid] = M[cur][tid];
    if (tid < NSTATE) {                     // Q[SEG-1] = b^T A^SEG
        float a = 0.f;
        #pragma unroll
        for (int k = 0; k < NSTATE; ++k) a = fmaf(sb[k], M[cur][k * NSTATE + tid], a);
        Q[(SEG - 1) * NSTATE + tid] = a;
    }
    if (tid < SEG) {                        // c_k = b . A^k b
        float a = 0.f;
        #pragma unroll
        for (int m = 0; m < NSTATE; ++m) a = fmaf(sb[m], vrev[(SEG - 1 - tid) * NSTATE + m], a);
        g_c[tid] = a;
    }
}

// ---------------- K1: injected state only.  V = sum_s A^{SEG-1-s} b x_s ----------------
__global__ void __launch_bounds__(256) k1_inject(const float* __restrict__ x) {
    __shared__ float4 sv4[SEG][4];
    const int tid = threadIdx.x;
    if (tid < SEG * 4) ((float4*)sv4)[tid] = ((const float4*)g_vrev4)[tid];
    __syncthreads();

    const int job = blockIdx.x * 256 + tid;     // 262144 jobs = (ch, seg)
    const int d = job & (DMODEL - 1);
    const int b = (job >> 10) & 3;
    const int g = job >> 12;

    const float* xp = x + ((size_t)(b * SEQ + g * SEG)) * DMODEL + d;
    float V[NSTATE];
    #pragma unroll
    for (int m = 0; m < NSTATE; ++m) V[m] = 0.f;

    #pragma unroll
    for (int s = 0; s < SEG; ++s) {
        const float xv = xp[(size_t)s * DMODEL];
        const float4 a0 = sv4[s][0], a1 = sv4[s][1], a2 = sv4[s][2], a3 = sv4[s][3];
        V[0]  = fmaf(a0.x, xv, V[0]);  V[1]  = fmaf(a0.y, xv, V[1]);
        V[2]  = fmaf(a0.z, xv, V[2]);  V[3]  = fmaf(a0.w, xv, V[3]);
        V[4]  = fmaf(a1.x, xv, V[4]);  V[5]  = fmaf(a1.y, xv, V[5]);
        V[6]  = fmaf(a1.z, xv, V[6]);  V[7]  = fmaf(a1.w, xv, V[7]);
        V[8]  = fmaf(a2.x, xv, V[8]);  V[9]  = fmaf(a2.y, xv, V[9]);
        V[10] = fmaf(a2.z, xv, V[10]); V[11] = fmaf(a2.w, xv, V[11]);
        V[12] = fmaf(a3.x, xv, V[12]); V[13] = fmaf(a3.y, xv, V[13]);
        V[14] = fmaf(a3.z, xv, V[14]); V[15] = fmaf(a3.w, xv, V[15]);
    }
    const int ch = b * DMODEL + d;
    float4* vp = g_V4 + ((size_t)g * NCH + ch) * 4;
    vp[0] = make_float4(V[0],  V[1],  V[2],  V[3]);
    vp[1] = make_float4(V[4],  V[5],  V[6],  V[7]);
    vp[2] = make_float4(V[8],  V[9],  V[10], V[11]);
    vp[3] = make_float4(V[12], V[13], V[14], V[15]);
}

// ---------------- K2: fused sequential prefix over segments ----------------
// 16 lanes per channel (lane = state dim m). H_{g+1} = A32 H_g + V_g; store entry states.
__global__ void __launch_bounds__(256) k2_prefix(void) {
    const int tid = threadIdx.x;
    const int m   = tid & 15;
    const int ch  = (blockIdx.x * 256 + tid) >> 4;     // 256 blocks -> 4096 channels

    float ar[NSTATE];
    #pragma unroll
    for (int n = 0; n < NSTATE; ++n) ar[n] = g_A32[m * NSTATE + n];

    const float* Vs = (const float*)g_V4;
    float*       Hs = (float*)g_H4;

    float h = 0.f;
    for (int g = 0; g < NSEGS; ++g) {
        const size_t off = ((size_t)g * NCH + ch) * NSTATE + m;   // coalesced
        Hs[off] = h;                                   // entry state of segment g
        const float v = Vs[off];
        float a0 = v, a1 = 0.f, a2 = 0.f, a3 = 0.f;
        #pragma unroll
        for (int n = 0; n < NSTATE; n += 4) {
            a0 = fmaf(ar[n + 0], __shfl_sync(0xffffffffu, h, n + 0, 16), a0);
            a1 = fmaf(ar[n + 1], __shfl_sync(0xffffffffu, h, n + 1, 16), a1);
            a2 = fmaf(ar[n + 2], __shfl_sync(0xffffffffu, h, n + 2, 16), a2);
            a3 = fmaf(ar[n + 3], __shfl_sync(0xffffffffu, h, n + 3, 16), a3);
        }
        h = (a0 + a1) + (a2 + a3);
    }
}

// ---------------- K3: full output  y = conv(x) + Q . H_seg  (single write, no RMW) ----
__global__ void __launch_bounds__(256) k3_fused(const float* __restrict__ x,
                                                float* __restrict__ out) {
    __shared__ float  sc[SEG];
    __shared__ float4 sQ4[SEG][4];
    const int tid = threadIdx.x;
    if (tid < SEG) sc[tid] = g_c[tid];
    if (tid < SEG * 4) ((float4*)sQ4)[tid] = ((const float4*)g_Q4)[tid];
    __syncthreads();

    const int job = blockIdx.x * 256 + tid;     // 262144 jobs = (ch, seg)
    const int d = job & (DMODEL - 1);
    const int b = (job >> 10) & 3;
    const int g = job >> 12;
    const int ch = b * DMODEL + d;

    const size_t base = ((size_t)(b * SEQ + g * SEG)) * DMODEL + d;
    const float* xp = x + base;
    float xs[SEG];
    #pragma unroll
    for (int s = 0; s < SEG; ++s) xs[s] = xp[(size_t)s * DMODEL];

    // entry state H: 4x LDG.128, warp footprint 2KB contiguous
    const float4* hp = g_H4 + ((size_t)g * NCH + ch) * 4;
    const float4 h0 = hp[0], h1 = hp[1], h2 = hp[2], h3 = hp[3];
    const float H[NSTATE] = {h0.x, h0.y, h0.z, h0.w, h1.x, h1.y, h1.z, h1.w,
                             h2.x, h2.y, h2.z, h2.w, h3.x, h3.y, h3.z, h3.w};

    float* op = out + base;
    #pragma unroll
    for (int rb = 0; rb < SEG; rb += 8) {
        float acc[8];
        // init with correction Q[r] . H
        #pragma unroll
        for (int i = 0; i < 8; ++i) {
            const float4 q0 = sQ4[rb + i][0], q1 = sQ4[rb + i][1];
            const float4 q2 = sQ4[rb + i][2], q3 = sQ4[rb + i][3];
            float a = q0.x * H[0];
            a = fmaf(q0.y, H[1],  a); a = fmaf(q0.z, H[2],  a); a = fmaf(q0.w, H[3],  a);
            a = fmaf(q1.x, H[4],  a); a = fmaf(q1.y, H[5],  a);
            a = fmaf(q1.z, H[6],  a); a = fmaf(q1.w, H[7],  a);
            a = fmaf(q2.x, H[8],  a); a = fmaf(q2.y, H[9],  a);
            a = fmaf(q2.z, H[10], a); a = fmaf(q2.w, H[11], a);
            a = fmaf(q3.x, H[12], a); a = fmaf(q3.y, H[13], a);
            a = fmaf(q3.z, H[14], a); a = fmaf(q3.w, H[15], a);
            acc[i] = a;
        }
        // triangular local convolution for outputs rb..rb+7
        #pragma unroll
        for (int s = 0; s < SEG; ++s) {
            if (s >= rb + 8) break;
            const float xv = xs[s];
            #pragma unroll
            for (int i = 0; i < 8; ++i)
                if (s <= rb + i) acc[i] = fmaf(sc[rb + i - s], xv, acc[i]);
        }
        #pragma unroll
        for (int i = 0; i < 8; ++i) op[(size_t)(rb + i) * DMODEL] = acc[i];
    }
}

// ---------------- launch ----------------
extern "C" void kernel_launch(void* const* d_in, const int* in_sizes, int n_in,
                              void* d_out, int out_size) {
    const float* x = nullptr; const float* A = nullptr; const float* bv = nullptr;
    for (int i = 0; i < n_in; ++i) {
        if      (in_sizes[i] == BATCH * SEQ * DMODEL) x  = (const float*)d_in[i];
        else if (in_sizes[i] == NSTATE * NSTATE)      A  = (const float*)d_in[i];
        else if (in_sizes[i] == NSTATE)               bv = (const float*)d_in[i];
    }
    float* out = (float*)d_out;

    k0_precompute<<<1, 256>>>(A, bv);
    k1_inject<<<(NCH * NSEGS) / 256, 256>>>(x);          // 1024 blocks
    k2_prefix<<<(NCH * NSTATE) / 256, 256>>>();          // 256 blocks
    k3_fused<<<(NCH * NSEGS) / 256, 256>>>(x, out);      // 1024 blocks
}